// round 14
// baseline (speedup 1.0000x reference)
#include <cuda_runtime.h>

// Problem constants: B=8, N=2048, D=768, two tensors -> 16 groups of 2048 rows
#define DDIM    768
#define NROWS   32768           // 2 * 8 * 2048 source rows
#define ROW4    512             // float4 per output row (2048/4)
#define GPC     4               // groups per chunk
#define NCHUNK  4               // 4 chunks x 4 groups = 16 groups
#define P1_BLOCKS (GPC * 256)   // 2048 rows/group / 8 warps = 256 blocks/group
#define P2_BLOCKS (GPC * 1024)  // 1024 x 16KB chunks per group

__device__ float g_src[NROWS];
__device__ float g_dst[NROWS];

// Phase 1 for groups [g0, g0+GPC): one warp per row, both dots in one pass.
__global__ __launch_bounds__(256) void edge_phase1(
    const float* __restrict__ H,
    const float* __restrict__ Dh,
    const float* __restrict__ W,     // [2*DDIM]: wa then wb
    const float* __restrict__ bptr,  // [1]
    int g0)
{
    int r    = g0 * 2048 + blockIdx.x * 8 + (threadIdx.x >> 5);
    int lane = threadIdx.x & 31;

    const float* X = (r < NROWS / 2) ? (H  + (size_t)r * DDIM)
                                     : (Dh + (size_t)(r - NROWS / 2) * DDIM);
    const float4* X4  = (const float4*)X;
    const float4* Wa4 = (const float4*)W;
    const float4* Wb4 = (const float4*)(W + DDIM);

    float sa = 0.f, sb = 0.f;
    #pragma unroll
    for (int k = 0; k < 6; k++) {                     // 192 float4 per row / 32 lanes
        int idx = lane + k * 32;
        float4 x  = __ldcs(&X4[idx]);
        float4 wa = __ldg(&Wa4[idx]);
        float4 wb = __ldg(&Wb4[idx]);
        sa = fmaf(x.x, wa.x, fmaf(x.y, wa.y, fmaf(x.z, wa.z, fmaf(x.w, wa.w, sa))));
        sb = fmaf(x.x, wb.x, fmaf(x.y, wb.y, fmaf(x.z, wb.z, fmaf(x.w, wb.w, sb))));
    }
    #pragma unroll
    for (int off = 16; off; off >>= 1) {
        sa += __shfl_xor_sync(0xffffffffu, sa, off);
        sb += __shfl_xor_sync(0xffffffffu, sb, off);
    }
    if (lane == 0) {
        g_src[r] = sa + __ldg(bptr);
        g_dst[r] = sb;
    }
    cudaTriggerProgrammaticLaunchCompletion();        // let dependent p2 chunk fly
}

// Phase 2 for groups [g0, g0+GPC): exact round-7 store body (39.4us shape).
// Triggers IMMEDIATELY so the next (independent) p1 chunk overlaps our writes;
// gates its own reads on the predecessor p1 chunk via GridDependencySync.
__global__ __launch_bounds__(256) void edge_phase2(float4* __restrict__ out, int g0)
{
    cudaTriggerProgrammaticLaunchCompletion();        // successor p1 has no dep on us
    cudaGridDependencySynchronize();                  // wait: our p1 chunk's writes
    asm volatile("" ::: "memory");                    // no load hoisting above sync

    const float*  src  = g_src;
    const float4* dst4 = (const float4*)g_dst;

    unsigned base = ((unsigned)g0 << 20) + blockIdx.x * 1024u;  // g0*1024*1024 float4
    #pragma unroll
    for (int it = 0; it < 4; it++) {
        unsigned v   = base + it * 256u + threadIdx.x;
        unsigned row = v >> 9;
        unsigned j4  = v & (ROW4 - 1);
        float  si = __ldg(&src[row]);
        float4 sd = __ldg(&dst4[((row >> 11) << 9) + j4]);
        float4 o;
        o.x = fmaxf(si + sd.x, 0.f);
        o.y = fmaxf(si + sd.y, 0.f);
        o.z = fmaxf(si + sd.z, 0.f);
        o.w = fmaxf(si + sd.w, 0.f);
        __stcs(&out[v], o);
    }
}

extern "C" void kernel_launch(void* const* d_in, const int* in_sizes, int n_in,
                              void* d_out, int out_size)
{
    const float* H  = (const float*)d_in[0];
    const float* Dh = (const float*)d_in[1];
    const float* W  = (const float*)d_in[2];
    const float* b  = (const float*)d_in[3];
    float4* out = (float4*)d_out;

    cudaLaunchAttribute attr[1];
    attr[0].id = cudaLaunchAttributeProgrammaticStreamSerialization;
    attr[0].val.programmaticStreamSerializationAllowed = 1;

    for (int c = 0; c < NCHUNK; c++) {
        int g0 = c * GPC;
        if (c == 0) {
            edge_phase1<<<P1_BLOCKS, 256>>>(H, Dh, W, b, g0);
        } else {
            cudaLaunchConfig_t cfg = {};
            cfg.gridDim  = dim3(P1_BLOCKS, 1, 1);
            cfg.blockDim = dim3(256, 1, 1);
            cfg.stream   = 0;
            cfg.attrs    = attr;
            cfg.numAttrs = 1;
            cudaLaunchKernelEx(&cfg, edge_phase1, H, Dh, W, b, g0);
        }
        cudaLaunchConfig_t cfg2 = {};
        cfg2.gridDim  = dim3(P2_BLOCKS, 1, 1);
        cfg2.blockDim = dim3(256, 1, 1);
        cfg2.stream   = 0;
        cfg2.attrs    = attr;
        cfg2.numAttrs = 1;
        cudaLaunchKernelEx(&cfg2, edge_phase2, out, g0);
    }
}

// round 15
// speedup vs baseline: 1.1905x; 1.1905x over previous
#include <cuda_runtime.h>

// Problem constants: B=8, N=2048, D=768, two tensors (H, doc_sents_h)
#define DDIM   768
#define NROWS  32768            // 2 * 8 * 2048 source rows
#define HALF   16384            // rows per tensor
#define ROW4   512              // float4 per output row (2048/4)

// Scratch: s_src (bias folded in) and s_dst per (tensor, batch, n)
__device__ float g_src[NROWS];
__device__ float g_dst[NROWS];

// Phase 1 over ONE tensor half (R7 body): one warp per row, both dots.
__global__ __launch_bounds__(256) void edge_phase1(
    const float* __restrict__ X,     // H or Dh base
    const float* __restrict__ W,     // [2*DDIM]: wa then wb
    const float* __restrict__ bptr,  // [1]
    int row0)                        // 0 for H, HALF for Dh (scratch offset)
{
    int rl   = blockIdx.x * 8 + (threadIdx.x >> 5);   // local row 0..16383
    int lane = threadIdx.x & 31;

    const float4* X4  = (const float4*)(X + (size_t)rl * DDIM);
    const float4* Wa4 = (const float4*)W;
    const float4* Wb4 = (const float4*)(W + DDIM);

    float sa = 0.f, sb = 0.f;
    #pragma unroll
    for (int k = 0; k < 6; k++) {                     // 192 float4 per row / 32 lanes
        int idx = lane + k * 32;
        float4 x  = __ldcs(&X4[idx]);
        float4 wa = __ldg(&Wa4[idx]);
        float4 wb = __ldg(&Wb4[idx]);
        sa = fmaf(x.x, wa.x, fmaf(x.y, wa.y, fmaf(x.z, wa.z, fmaf(x.w, wa.w, sa))));
        sb = fmaf(x.x, wb.x, fmaf(x.y, wb.y, fmaf(x.z, wb.z, fmaf(x.w, wb.w, sb))));
    }
    #pragma unroll
    for (int off = 16; off; off >>= 1) {
        sa += __shfl_xor_sync(0xffffffffu, sa, off);
        sb += __shfl_xor_sync(0xffffffffu, sb, off);
    }
    if (lane == 0) {
        int r = row0 + rl;
        g_src[r] = sa + __ldg(bptr);
        g_dst[r] = sb;
    }
}

// Phase 2 over half the output (R7 body, 39.4us/268MB shape):
// each block writes 1024 CONSECUTIVE float4 (16 KB), streaming stores.
__global__ __launch_bounds__(256) void edge_phase2(float4* __restrict__ out,
                                                   unsigned blk0)
{
    const float*  __restrict__ src  = g_src;
    const float4* __restrict__ dst4 = (const float4*)g_dst;

    unsigned base = (blockIdx.x + blk0) * 1024u;
    #pragma unroll
    for (int it = 0; it < 4; it++) {
        unsigned v   = base + it * 256u + threadIdx.x;
        unsigned row = v >> 9;                        // /ROW4
        unsigned j4  = v & (ROW4 - 1);
        float  si = __ldg(&src[row]);
        float4 sd = __ldg(&dst4[((row >> 11) << 9) + j4]);  // group = row/2048
        float4 o;
        o.x = fmaxf(si + sd.x, 0.f);
        o.y = fmaxf(si + sd.y, 0.f);
        o.z = fmaxf(si + sd.z, 0.f);
        o.w = fmaxf(si + sd.w, 0.f);
        __stcs(&out[v], o);
    }
}

extern "C" void kernel_launch(void* const* d_in, const int* in_sizes, int n_in,
                              void* d_out, int out_size)
{
    const float* H  = (const float*)d_in[0];
    const float* Dh = (const float*)d_in[1];
    const float* W  = (const float*)d_in[2];
    const float* b  = (const float*)d_in[3];
    float4* out = (float4*)d_out;

    // One aux stream + fork/join events, created once (host objects only —
    // no device memory). Non-blocking to avoid implicit legacy-stream sync.
    static cudaStream_t s1 = nullptr;
    static cudaEvent_t  ev_fork = nullptr, ev_join = nullptr;
    if (s1 == nullptr) {
        cudaStreamCreateWithFlags(&s1, cudaStreamNonBlocking);
        cudaEventCreateWithFlags(&ev_fork, cudaEventDisableTiming);
        cudaEventCreateWithFlags(&ev_join, cudaEventDisableTiming);
    }

    // Branch A (default stream): H reduction, then H-half output.
    edge_phase1<<<2048, 256>>>(H, W, b, 0);
    cudaEventRecord(ev_fork, 0);

    // Branch B (aux stream): forked after p1(H) so its reads overlap p2a's
    // writes; Dh reduction, then Dh-half output.
    cudaStreamWaitEvent(s1, ev_fork, 0);
    edge_phase1<<<2048, 256, 0, s1>>>(Dh, W, b, HALF);
    edge_phase2<<<8192, 256, 0, s1>>>(out, 8192);     // groups 8..15
    cudaEventRecord(ev_join, s1);

    edge_phase2<<<8192, 256>>>(out, 0);               // groups 0..7 (default stream)
    cudaStreamWaitEvent(0, ev_join, 0);               // join branches
}